// round 1
// baseline (speedup 1.0000x reference)
#include <cuda_runtime.h>
#include <math.h>
#include <stdint.h>

// Problem constants
#define NN 100000
#define NE 1600000
#define NE2 (NE + NN)

// ---------------------------------------------------------------------------
// Scratch (device globals — no allocation allowed)
// ---------------------------------------------------------------------------
__device__ float g_h[(size_t)NN * 128];   // per-layer linear output (max [N,128])
__device__ float g_out[(size_t)NN * 64];  // per-layer aggregated output
__device__ float g_asrc[NN * 8];
__device__ float g_adst[NN * 8];
__device__ int   g_rowptr[NN + 1];
__device__ int   g_cursor[NN];
__device__ int   g_csrc[NE2];
__device__ int   g_cnt[NN];

// ---------------------------------------------------------------------------
// CSR build (dst-sorted adjacency incl. self-loops), reused for all 3 layers
// ---------------------------------------------------------------------------
__global__ void k_deg_init() {
    int i = blockIdx.x * blockDim.x + threadIdx.x;
    if (i < NN) g_cnt[i] = 1;  // self loop
}

__global__ void k_hist(const int* __restrict__ edst) {
    int e = blockIdx.x * blockDim.x + threadIdx.x;
    if (e < NE) atomicAdd(&g_cnt[edst[e]], 1);
}

__global__ void k_scan() {
    __shared__ int sm[1024];
    int t = threadIdx.x;
    const int CH = (NN + 1023) / 1024;  // 98
    int b = t * CH;
    int e = b + CH; if (e > NN) e = NN;
    int s = 0;
    for (int i = b; i < e && i < NN; i++) s += g_cnt[i];
    sm[t] = s;
    __syncthreads();
    // Hillis-Steele inclusive scan
    for (int off = 1; off < 1024; off <<= 1) {
        int v = (t >= off) ? sm[t - off] : 0;
        __syncthreads();
        sm[t] += v;
        __syncthreads();
    }
    int run = sm[t] - s;  // exclusive prefix
    for (int i = b; i < e && i < NN; i++) {
        g_rowptr[i] = run;
        g_cursor[i] = run;
        run += g_cnt[i];
    }
    if (t == 1023) g_rowptr[NN] = sm[1023];
}

__global__ void k_scatter(const int* __restrict__ esrc, const int* __restrict__ edst) {
    int i = blockIdx.x * blockDim.x + threadIdx.x;
    if (i < NN) {
        int p = atomicAdd(&g_cursor[i], 1);
        g_csrc[p] = i;  // self loop
    } else if (i < NN + NE) {
        int e = i - NN;
        int d = edst[e];
        int p = atomicAdd(&g_cursor[d], 1);
        g_csrc[p] = esrc[e];
    }
}

// ---------------------------------------------------------------------------
// fp32 tiled GEMM:  C[N, M] = [A1 | A2] @ B,  split-K (K1 from A1, K2 from A2)
// BM=128, BN=64, BK=16, 256 threads, thread tile 8x4
// ---------------------------------------------------------------------------
__global__ __launch_bounds__(256) void k_gemm(
    const float* __restrict__ A1, int K1,
    const float* __restrict__ A2, int K2,
    const float* __restrict__ B, float* __restrict__ C, int M)
{
    __shared__ float As[16][128];
    __shared__ float Bs[16][64];
    int tid = threadIdx.x;
    int tx = tid & 15, ty = tid >> 4;
    int rowBase = blockIdx.x * 128;
    int colBase = blockIdx.y * 64;

    float acc[8][4];
#pragma unroll
    for (int i = 0; i < 8; i++)
#pragma unroll
        for (int j = 0; j < 4; j++) acc[i][j] = 0.f;

    int K = K1 + K2;
    for (int k0 = 0; k0 < K; k0 += 16) {
        const float* A;
        int Ks, kk;
        if (k0 < K1) { A = A1; Ks = K1; kk = k0; }
        else         { A = A2; Ks = K2; kk = k0 - K1; }
        // load A tile: 2 float4 per thread
#pragma unroll
        for (int it = 0; it < 2; it++) {
            int idx = tid + it * 256;
            int r = idx >> 2;          // 0..127
            int k4 = (idx & 3) * 4;
            int gr = rowBase + r;
            float4 f = make_float4(0.f, 0.f, 0.f, 0.f);
            if (gr < NN) f = *(const float4*)(A + (size_t)gr * Ks + kk + k4);
            As[k4 + 0][r] = f.x;
            As[k4 + 1][r] = f.y;
            As[k4 + 2][r] = f.z;
            As[k4 + 3][r] = f.w;
        }
        // load B tile: 1 float4 per thread
        {
            int r = tid >> 4;          // 0..15
            int c4 = (tid & 15) * 4;
            float4 f = *(const float4*)(B + (size_t)(k0 + r) * M + colBase + c4);
            Bs[r][c4 + 0] = f.x;
            Bs[r][c4 + 1] = f.y;
            Bs[r][c4 + 2] = f.z;
            Bs[r][c4 + 3] = f.w;
        }
        __syncthreads();
#pragma unroll
        for (int k = 0; k < 16; k++) {
            float a[8], b[4];
#pragma unroll
            for (int i = 0; i < 8; i++) a[i] = As[k][ty * 8 + i];
#pragma unroll
            for (int j = 0; j < 4; j++) b[j] = Bs[k][tx * 4 + j];
#pragma unroll
            for (int i = 0; i < 8; i++)
#pragma unroll
                for (int j = 0; j < 4; j++) acc[i][j] += a[i] * b[j];
        }
        __syncthreads();
    }
#pragma unroll
    for (int i = 0; i < 8; i++) {
        int gr = rowBase + ty * 8 + i;
        if (gr < NN) {
            float4 f = make_float4(acc[i][0], acc[i][1], acc[i][2], acc[i][3]);
            *(float4*)(C + (size_t)gr * M + colBase + tx * 4) = f;
        }
    }
}

// ---------------------------------------------------------------------------
// attention coefficients: a_src[n,h] = sum_c h[n,h,c]*att_src[h,c]  (same dst)
// ---------------------------------------------------------------------------
template <int C>
__global__ void k_attn(const float* __restrict__ h,
                       const float* __restrict__ ats,
                       const float* __restrict__ atd)
{
    int idx = blockIdx.x * blockDim.x + threadIdx.x;
    if (idx >= NN * 8) return;
    int n = idx >> 3, hd = idx & 7;
    const float* hp = h + (size_t)n * (8 * C) + hd * C;
    float s = 0.f, d = 0.f;
#pragma unroll
    for (int c = 0; c < C; c++) {
        float v = hp[c];
        s += v * ats[hd * C + c];
        d += v * atd[hd * C + c];
    }
    g_asrc[idx] = s;
    g_adst[idx] = d;
}

// ---------------------------------------------------------------------------
// Aggregation: one warp per dst node. lane -> (head = lane>>2, VEC=C/4 chans).
// Two-phase softmax (max, then exp/sum/acc), fused bias (+PReLU) epilogue.
// FINAL: head-mean + bias + log_softmax fused.
// ---------------------------------------------------------------------------
template <int C, bool FINAL>
__global__ __launch_bounds__(256) void k_agg(
    const float* __restrict__ h,
    const float* __restrict__ bias,
    const float* __restrict__ prelu_a,
    float* __restrict__ out)
{
    constexpr int VEC = C / 4;
    int warp = (blockIdx.x * blockDim.x + threadIdx.x) >> 5;
    if (warp >= NN) return;
    int lane = threadIdx.x & 31;
    int head = lane >> 2;

    int beg = g_rowptr[warp];
    int end = g_rowptr[warp + 1];
    float ad = g_adst[warp * 8 + head];

    // phase 1: per-head max (lanes of a head split edges mod 4)
    float m = -3.0e38f;
    for (int i = beg + (lane & 3); i < end; i += 4) {
        int s = g_csrc[i];
        float e = g_asrc[s * 8 + head] + ad;
        e = (e < 0.f) ? 0.2f * e : e;
        m = fmaxf(m, e);
    }
    m = fmaxf(m, __shfl_xor_sync(0xffffffffu, m, 1));
    m = fmaxf(m, __shfl_xor_sync(0xffffffffu, m, 2));

    // phase 2: exp-sum + weighted accumulation (warp walks edges together)
    float ssum = 0.f;
    float acc[VEC];
#pragma unroll
    for (int j = 0; j < VEC; j++) acc[j] = 0.f;

    for (int i = beg; i < end; ++i) {
        int s = g_csrc[i];
        float e = g_asrc[s * 8 + head] + ad;
        e = (e < 0.f) ? 0.2f * e : e;
        float w = __expf(e - m);
        ssum += w;
        const float* hp = h + (size_t)s * (8 * C) + lane * VEC;
        if (C == 8) {
            float2 v = *(const float2*)hp;
            acc[0] += w * v.x;
            acc[1] += w * v.y;
        } else {
            float4 v = *(const float4*)hp;
            acc[0] += w * v.x;
            acc[1] += w * v.y;
            acc[2] += w * v.z;
            acc[3] += w * v.w;
        }
    }
    float inv = 1.f / (ssum + 1e-16f);

    if (!FINAL) {
        float p = prelu_a[0];
        float v[VEC];
#pragma unroll
        for (int j = 0; j < VEC; j++) {
            float t = acc[j] * inv + bias[lane * VEC + j];
            v[j] = (t >= 0.f) ? t : p * t;
        }
        if (C == 8) {
            float2 f = make_float2(v[0], v[1]);
            *(float2*)(out + (size_t)warp * 64 + lane * 2) = f;
        }
    } else {
        // v[j] per (head, channel block); mean over heads (lanes stride 4)
        float v[4];
#pragma unroll
        for (int j = 0; j < 4; j++) v[j] = acc[j] * inv;
#pragma unroll
        for (int j = 0; j < 4; j++) {
            v[j] += __shfl_xor_sync(0xffffffffu, v[j], 4);
            v[j] += __shfl_xor_sync(0xffffffffu, v[j], 8);
            v[j] += __shfl_xor_sync(0xffffffffu, v[j], 16);
            v[j] = v[j] * 0.125f + bias[(lane & 3) * 4 + j];
        }
        // log_softmax over the 16 channels (replicated across groups of 4 lanes)
        float mx = fmaxf(fmaxf(v[0], v[1]), fmaxf(v[2], v[3]));
        mx = fmaxf(mx, __shfl_xor_sync(0xffffffffu, mx, 1));
        mx = fmaxf(mx, __shfl_xor_sync(0xffffffffu, mx, 2));
        float se = 0.f;
#pragma unroll
        for (int j = 0; j < 4; j++) se += __expf(v[j] - mx);
        se += __shfl_xor_sync(0xffffffffu, se, 1);
        se += __shfl_xor_sync(0xffffffffu, se, 2);
        float lse = mx + __logf(se);
        if (lane < 4) {
            float4 f = make_float4(v[0] - lse, v[1] - lse, v[2] - lse, v[3] - lse);
            *(float4*)(out + (size_t)warp * 16 + lane * 4) = f;
        }
    }
}

// ---------------------------------------------------------------------------
// Launch
// ---------------------------------------------------------------------------
extern "C" void kernel_launch(void* const* d_in, const int* in_sizes, int n_in,
                              void* d_out, int out_size)
{
    const float* x   = (const float*)d_in[0];
    const int*   ei  = (const int*)d_in[1];
    const float* W1  = (const float*)d_in[2];
    const float* as1 = (const float*)d_in[3];
    const float* ad1 = (const float*)d_in[4];
    const float* b1  = (const float*)d_in[5];
    const float* W2  = (const float*)d_in[6];
    const float* as2 = (const float*)d_in[7];
    const float* ad2 = (const float*)d_in[8];
    const float* b2  = (const float*)d_in[9];
    const float* W3  = (const float*)d_in[10];
    const float* as3 = (const float*)d_in[11];
    const float* ad3 = (const float*)d_in[12];
    const float* b3  = (const float*)d_in[13];
    const float* p1  = (const float*)d_in[14];
    const float* p2  = (const float*)d_in[15];
    float* out = (float*)d_out;

    void *ph, *po;
    cudaGetSymbolAddress(&ph, g_h);
    cudaGetSymbolAddress(&po, g_out);
    float* h = (float*)ph;
    float* o = (float*)po;

    const int* esrc = ei;
    const int* edst = ei + NE;

    // CSR build (shared by all layers)
    k_deg_init<<<(NN + 255) / 256, 256>>>();
    k_hist<<<(NE + 255) / 256, 256>>>(edst);
    k_scan<<<1, 1024>>>();
    k_scatter<<<(NN + NE + 255) / 256, 256>>>(esrc, edst);

    dim3 gemm_g1((NN + 127) / 128, 1);
    dim3 gemm_g3((NN + 127) / 128, 2);
    int attn_blocks = (NN * 8 + 255) / 256;
    int agg_blocks  = (NN * 32 + 255) / 256;

    // Layer 1: h = x @ W1 ; aggregate ; +b1 ; PReLU(p1)
    k_gemm<<<gemm_g1, 256>>>(x, 256, (const float*)0, 0, W1, h, 64);
    k_attn<8><<<attn_blocks, 256>>>(h, as1, ad1);
    k_agg<8, false><<<agg_blocks, 256>>>(h, b1, p1, o);

    // Layer 2: h = [x | o] @ W2 (split-K) ; aggregate ; +b2 ; PReLU(p2)
    k_gemm<<<gemm_g1, 256>>>(x, 256, o, 64, W2, h, 64);
    k_attn<8><<<attn_blocks, 256>>>(h, as2, ad2);
    k_agg<8, false><<<agg_blocks, 256>>>(h, b2, p2, o);

    // Layer 3: h = o @ W3 ; aggregate ; head-mean ; +b3 ; log_softmax
    k_gemm<<<gemm_g3, 256>>>(o, 64, (const float*)0, 0, W3, h, 128);
    k_attn<16><<<attn_blocks, 256>>>(h, as3, ad3);
    k_agg<16, true><<<agg_blocks, 256>>>(h, b3, (const float*)0, out);
}